// round 1
// baseline (speedup 1.0000x reference)
#include <cuda_runtime.h>
#include <cuda_bf16.h>
#include <cstdint>
#include <cstddef>

// Problem constants (fixed shapes for this problem instance)
#define T_STEPS 1000
#define BATCH   64
#define NDIM    512
#define KDIM    512
#define MROWS   (BATCH * T_STEPS)   // 64000

static constexpr size_t PLANE      = (size_t)BATCH * NDIM;          // 32768
static constexpr size_t STATES_OFF = (size_t)T_STEPS * PLANE;       // 32,768,000  (outputs plane size)
static constexpr size_t DEC_OFF    = STATES_OFF + 3 * STATES_OFF;   // 131,072,000 (after states [T,3,B,N])

// Scratch: feedforward currents I[B*T, N] and readout partials r[T*B]
__device__ __align__(16) float g_I[(size_t)MROWS * NDIM];
__device__ float g_r[T_STEPS * BATCH];

// ---------------------------------------------------------------------------
// Kernel 1: I = X @ W1^T   (X: [M,K] row-major, W1: [N,K] row-major -> NT GEMM)
// Classic 128x128 tile, 8x8 per thread, BK=16, 256 threads.
// ---------------------------------------------------------------------------
__global__ __launch_bounds__(256) void sgemm_nt_kernel(const float* __restrict__ X,
                                                       const float* __restrict__ W)
{
    __shared__ float sX[16][128];
    __shared__ float sW[16][128];

    const int bm  = blockIdx.x * 128;
    const int bn  = blockIdx.y * 128;
    const int tid = threadIdx.x;
    const int tx  = tid & 15;        // 0..15 -> n sub-tile
    const int ty  = tid >> 4;        // 0..15 -> m sub-tile
    const int lr  = tid >> 2;        // loader row 0..63
    const int lk  = (tid & 3) << 2;  // loader k offset {0,4,8,12}

    float acc[8][8];
    #pragma unroll
    for (int i = 0; i < 8; i++)
        #pragma unroll
        for (int j = 0; j < 8; j++)
            acc[i][j] = 0.f;

    for (int k0 = 0; k0 < KDIM; k0 += 16) {
        #pragma unroll
        for (int rr = 0; rr < 2; rr++) {
            const int row = lr + rr * 64;
            float4 xv = *(const float4*)(X + (size_t)(bm + row) * KDIM + k0 + lk);
            sX[lk + 0][row] = xv.x; sX[lk + 1][row] = xv.y;
            sX[lk + 2][row] = xv.z; sX[lk + 3][row] = xv.w;
            float4 wv = *(const float4*)(W + (size_t)(bn + row) * KDIM + k0 + lk);
            sW[lk + 0][row] = wv.x; sW[lk + 1][row] = wv.y;
            sW[lk + 2][row] = wv.z; sW[lk + 3][row] = wv.w;
        }
        __syncthreads();

        #pragma unroll
        for (int k = 0; k < 16; k++) {
            float xr[8], wr[8];
            *(float4*)&xr[0] = *(const float4*)&sX[k][ty * 8];
            *(float4*)&xr[4] = *(const float4*)&sX[k][ty * 8 + 4];
            *(float4*)&wr[0] = *(const float4*)&sW[k][tx * 8];
            *(float4*)&wr[4] = *(const float4*)&sW[k][tx * 8 + 4];
            #pragma unroll
            for (int i = 0; i < 8; i++)
                #pragma unroll
                for (int j = 0; j < 8; j++)
                    acc[i][j] = fmaf(xr[i], wr[j], acc[i][j]);
        }
        __syncthreads();
    }

    #pragma unroll
    for (int i = 0; i < 8; i++) {
        const size_t rowoff = (size_t)(bm + ty * 8 + i) * NDIM + bn + tx * 8;
        #pragma unroll
        for (int j = 0; j < 8; j += 4) {
            float4 v4 = make_float4(acc[i][j], acc[i][j + 1], acc[i][j + 2], acc[i][j + 3]);
            *(float4*)(g_I + rowoff + j) = v4;
        }
    }
}

// ---------------------------------------------------------------------------
// Kernel 2: per-neuron Izhikevich scan over T steps. One thread per (b,n).
// Writes outputs[t,b,n], states[t,{u,v,s},b,n].
// ---------------------------------------------------------------------------
struct NeuronP { float TS, V2, V1, V0, KA, Bp, TH, Cc, D; };

__device__ __forceinline__ void snn_step(float Ic, int t, int g,
                                         const NeuronP& P, float& u, float& v,
                                         float* __restrict__ out)
{
    float t0 = P.V0 - u + Ic;
    t0 = fmaf(P.V1, v, t0);
    t0 = fmaf(P.V2, v * v, t0);
    const float vn = fmaf(P.TS, t0, v);
    const float un = fmaf(P.KA, fmaf(P.Bp, v, -u), u);
    const bool  sp = (vn - P.TH) > 0.f;
    const float s  = sp ? 1.f : 0.f;
    const float vo = sp ? P.Cc : vn;
    const float uo = sp ? (un + P.D) : un;

    out[(size_t)t * PLANE + g] = s;                        // outputs plane
    const size_t sb = STATES_OFF + (size_t)t * (3 * PLANE) + g;
    out[sb]             = uo;                              // states[t][0] = u
    out[sb + PLANE]     = vo;                              // states[t][1] = v
    out[sb + 2 * PLANE] = s;                               // states[t][2] = s
    u = uo; v = vo;
}

__global__ __launch_bounds__(128) void scan_kernel(
    const float* __restrict__ st,
    const float* __restrict__ pa,  const float* __restrict__ pb,
    const float* __restrict__ pc,  const float* __restrict__ pd,
    const float* __restrict__ pv2, const float* __restrict__ pv1,
    const float* __restrict__ pv0, const float* __restrict__ ptau,
    const float* __restrict__ pth, const float* __restrict__ pts,
    float* __restrict__ out)
{
    const int g = blockIdx.x * 128 + threadIdx.x;   // 0..32767, g = b*512 + n
    const int n = g & (NDIM - 1);

    NeuronP P;
    P.TS = pts[n];
    P.V2 = pv2[n]; P.V1 = pv1[n]; P.V0 = pv0[n];
    P.KA = P.TS / ptau[n] * pa[n];
    P.Bp = pb[n]; P.TH = pth[n]; P.Cc = pc[n]; P.D = pd[n];

    float u = st[g];
    float v = st[PLANE + g];

    const float* Ip = g_I + (size_t)(g >> 9) * ((size_t)T_STEPS * NDIM) + n;

    // Double-buffered prefetch, depth 8 each: loads for the next 8 steps are
    // in flight while computing/storing the current 8.
    float bufA[8], bufB[8];
    #pragma unroll
    for (int p = 0; p < 8; p++) bufA[p] = Ip[(size_t)p * NDIM];

    #pragma unroll 1
    for (int t0 = 0; t0 < 992; t0 += 16) {
        #pragma unroll
        for (int p = 0; p < 8; p++) bufB[p] = Ip[(size_t)(t0 + 8 + p) * NDIM];
        #pragma unroll
        for (int p = 0; p < 8; p++) snn_step(bufA[p], t0 + p, g, P, u, v, out);
        #pragma unroll
        for (int p = 0; p < 8; p++) bufA[p] = Ip[(size_t)(t0 + 16 + p) * NDIM];
        #pragma unroll
        for (int p = 0; p < 8; p++) snn_step(bufB[p], t0 + 8 + p, g, P, u, v, out);
    }
    // Tail: t = 992..999 already resident in bufA (loaded in last iteration).
    #pragma unroll
    for (int p = 0; p < 8; p++) snn_step(bufA[p], 992 + p, g, P, u, v, out);
}

// ---------------------------------------------------------------------------
// Kernel 3: r[t*B+b] = sum_n s[t,b,n] * W2[n]   (reads the outputs plane)
// One block per (t,b) row of 512; 128 threads, 4 elems each.
// ---------------------------------------------------------------------------
__global__ __launch_bounds__(128) void readout_reduce_kernel(
    const float* __restrict__ out, const float* __restrict__ W2)
{
    const int tb = blockIdx.x;                         // t*BATCH + b
    const float* sp = out + (size_t)tb * NDIM;
    const int tid = threadIdx.x;

    float sum = 0.f;
    #pragma unroll
    for (int j = 0; j < 4; j++) {
        const int n = tid + j * 128;
        sum = fmaf(sp[n], W2[n], sum);
    }
    #pragma unroll
    for (int o = 16; o > 0; o >>= 1)
        sum += __shfl_xor_sync(0xffffffffu, sum, o);

    __shared__ float ws[4];
    if ((tid & 31) == 0) ws[tid >> 5] = sum;
    __syncthreads();
    if (tid == 0) g_r[tb] = (ws[0] + ws[1]) + (ws[2] + ws[3]);
}

// ---------------------------------------------------------------------------
// Kernel 4: li[t,b] = leak*li[t-1,b] + r[t,b]; write decoded plane.
// ---------------------------------------------------------------------------
__global__ void li_kernel(const float* __restrict__ stLI,
                          const float* __restrict__ leak,
                          float* __restrict__ out)
{
    const int b = threadIdx.x;            // 64 threads
    float li = stLI[b];
    const float lk = leak[0];
    #pragma unroll 4
    for (int t = 0; t < T_STEPS; t++) {
        li = fmaf(lk, li, g_r[t * BATCH + b]);
        out[DEC_OFF + (size_t)t * BATCH + b] = li;
    }
}

// ---------------------------------------------------------------------------
extern "C" void kernel_launch(void* const* d_in, const int* in_sizes, int n_in,
                              void* d_out, int out_size)
{
    const float* x    = (const float*)d_in[0];   // input_batch [B,T,N]
    const float* st   = (const float*)d_in[1];   // state_snn [3,B,N]
    const float* stLI = (const float*)d_in[2];   // state_LI [B,1]
    const float* W1   = (const float*)d_in[3];   // [N,N]
    const float* W2   = (const float*)d_in[4];   // [1,N]
    const float* a_   = (const float*)d_in[5];
    const float* b_   = (const float*)d_in[6];
    const float* c_   = (const float*)d_in[7];
    const float* d_   = (const float*)d_in[8];
    const float* v2_  = (const float*)d_in[9];
    const float* v1_  = (const float*)d_in[10];
    const float* v0_  = (const float*)d_in[11];
    const float* tau_ = (const float*)d_in[12];
    const float* th_  = (const float*)d_in[13];
    const float* lk_  = (const float*)d_in[14];
    const float* ts_  = (const float*)d_in[15];
    float* out = (float*)d_out;

    dim3 ggrid(MROWS / 128, NDIM / 128);   // (500, 4)
    sgemm_nt_kernel<<<ggrid, 256>>>(x, W1);
    scan_kernel<<<(BATCH * NDIM) / 128, 128>>>(st, a_, b_, c_, d_, v2_, v1_,
                                               v0_, tau_, th_, ts_, out);
    readout_reduce_kernel<<<T_STEPS * BATCH, 128>>>(out, W2);
    li_kernel<<<1, BATCH>>>(stLI, lk_, out);
}

// round 3
// speedup vs baseline: 1.3812x; 1.3812x over previous
#include <cuda_runtime.h>
#include <cstdint>
#include <cstddef>
#include <cmath>

// Problem constants
#define T_STEPS 1000
#define BATCH   64
#define NDIM    512
#define KDIM    512
#define MROWS   (BATCH * T_STEPS)   // 64000

static constexpr size_t PLANE      = (size_t)BATCH * NDIM;          // 32768
static constexpr size_t STATES_OFF = (size_t)T_STEPS * PLANE;       // outputs plane elems
static constexpr size_t DEC_OFF    = STATES_OFF + 3 * STATES_OFF;   // after states [T,3,B,N]

// Scratch
__device__ __align__(16) float g_I[(size_t)MROWS * NDIM];
__device__ float g_r[T_STEPS * BATCH];

// ---------------------------------------------------------------------------
// tf32 helpers (sm_80+ compatible — NO sm_100a-only instructions anywhere)
// ---------------------------------------------------------------------------
__device__ __forceinline__ uint32_t tf32_rna_bits(float x) {
    uint32_t u;
    asm("cvt.rna.tf32.f32 %0, %1;" : "=r"(u) : "f"(x));
    return u;
}

__device__ __forceinline__ void mma_tf32(float* c, const uint32_t* a, const uint32_t* b) {
    asm volatile(
        "mma.sync.aligned.m16n8k8.row.col.f32.tf32.tf32.f32 "
        "{%0,%1,%2,%3}, {%4,%5,%6,%7}, {%8,%9}, {%0,%1,%2,%3};\n"
        : "+f"(c[0]), "+f"(c[1]), "+f"(c[2]), "+f"(c[3])
        : "r"(a[0]), "r"(a[1]), "r"(a[2]), "r"(a[3]), "r"(b[0]), "r"(b[1]));
}

// ---------------------------------------------------------------------------
// Kernel 1: I = X @ W1^T  (NT GEMM) via mma.sync tf32, 3-product split.
// CTA tile 128x128, BK=32, 8 warps (4x2), warp tile 32x64.
// smem layout per buffer (floats, stride 36 per row of 32 + 4 pad):
//   Ahi[128*36] Alo[128*36] Bhi[128*36] Blo[128*36]  = 18432 floats = 72KB
// double buffered -> 144KB dynamic smem.
// ---------------------------------------------------------------------------
#define STRF 36
#define TILEF (128 * STRF)          // floats per sub-tile
#define BUleF (4 * TILEF)           // floats per buffer

struct LdgRegs { float4 a[4]; float4 b[4]; };

__device__ __forceinline__ void ldg_chunk(LdgRegs& r, const float* __restrict__ X,
                                          const float* __restrict__ W,
                                          int bm, int bn, int ck, int tid)
{
    const int row = tid >> 1;
    const int kb  = (tid & 1) * 16;
    const float4* xa = (const float4*)(X + (size_t)(bm + row) * KDIM + ck * 32 + kb);
    const float4* wa = (const float4*)(W + (size_t)(bn + row) * KDIM + ck * 32 + kb);
    #pragma unroll
    for (int j = 0; j < 4; j++) r.a[j] = xa[j];
    #pragma unroll
    for (int j = 0; j < 4; j++) r.b[j] = wa[j];
}

__device__ __forceinline__ void split4(const float4 v, float4& h, float4& l) {
    h.x = __uint_as_float(tf32_rna_bits(v.x));
    h.y = __uint_as_float(tf32_rna_bits(v.y));
    h.z = __uint_as_float(tf32_rna_bits(v.z));
    h.w = __uint_as_float(tf32_rna_bits(v.w));
    l.x = __uint_as_float(tf32_rna_bits(v.x - h.x));
    l.y = __uint_as_float(tf32_rna_bits(v.y - h.y));
    l.z = __uint_as_float(tf32_rna_bits(v.z - h.z));
    l.w = __uint_as_float(tf32_rna_bits(v.w - h.w));
}

__device__ __forceinline__ void sts_chunk(float* buf, const LdgRegs& r, int tid)
{
    const int row = tid >> 1;
    const int kb  = (tid & 1) * 16;
    float* sAhi = buf;
    float* sAlo = buf + TILEF;
    float* sBhi = buf + 2 * TILEF;
    float* sBlo = buf + 3 * TILEF;
    #pragma unroll
    for (int j = 0; j < 4; j++) {
        float4 h, l;
        split4(r.a[j], h, l);
        *(float4*)(sAhi + row * STRF + kb + j * 4) = h;
        *(float4*)(sAlo + row * STRF + kb + j * 4) = l;
    }
    #pragma unroll
    for (int j = 0; j < 4; j++) {
        float4 h, l;
        split4(r.b[j], h, l);
        *(float4*)(sBhi + row * STRF + kb + j * 4) = h;
        *(float4*)(sBlo + row * STRF + kb + j * 4) = l;
    }
}

__device__ __forceinline__ void compute_chunk(const float* buf, float (&acc)[2][8][4],
                                              int wm, int wn, int lane)
{
    const float* sAhi = buf;
    const float* sAlo = buf + TILEF;
    const float* sBhi = buf + 2 * TILEF;
    const float* sBlo = buf + 3 * TILEF;
    const int lq = lane >> 2;        // 0..7
    const int lr = lane & 3;         // 0..3

    #pragma unroll
    for (int kk = 0; kk < 32; kk += 8) {
        uint32_t Ah[2][4], Al[2][4], Bh[8][2], Bl[8][2];
        #pragma unroll
        for (int mt = 0; mt < 2; mt++) {
            const int r0 = wm * 32 + mt * 16 + lq;
            const int c0 = kk + lr;
            Ah[mt][0] = __float_as_uint(sAhi[r0 * STRF + c0]);
            Ah[mt][1] = __float_as_uint(sAhi[(r0 + 8) * STRF + c0]);
            Ah[mt][2] = __float_as_uint(sAhi[r0 * STRF + c0 + 4]);
            Ah[mt][3] = __float_as_uint(sAhi[(r0 + 8) * STRF + c0 + 4]);
            Al[mt][0] = __float_as_uint(sAlo[r0 * STRF + c0]);
            Al[mt][1] = __float_as_uint(sAlo[(r0 + 8) * STRF + c0]);
            Al[mt][2] = __float_as_uint(sAlo[r0 * STRF + c0 + 4]);
            Al[mt][3] = __float_as_uint(sAlo[(r0 + 8) * STRF + c0 + 4]);
        }
        #pragma unroll
        for (int nt = 0; nt < 8; nt++) {
            const int nr = wn * 64 + nt * 8 + lq;
            const int c0 = kk + lr;
            Bh[nt][0] = __float_as_uint(sBhi[nr * STRF + c0]);
            Bh[nt][1] = __float_as_uint(sBhi[nr * STRF + c0 + 4]);
            Bl[nt][0] = __float_as_uint(sBlo[nr * STRF + c0]);
            Bl[nt][1] = __float_as_uint(sBlo[nr * STRF + c0 + 4]);
        }
        #pragma unroll
        for (int mt = 0; mt < 2; mt++)
            #pragma unroll
            for (int nt = 0; nt < 8; nt++) {
                mma_tf32(acc[mt][nt], Ah[mt], Bh[nt]);
                mma_tf32(acc[mt][nt], Ah[mt], Bl[nt]);
                mma_tf32(acc[mt][nt], Al[mt], Bh[nt]);
            }
    }
}

__global__ __launch_bounds__(256, 1) void gemm_tf32_kernel(const float* __restrict__ X,
                                                           const float* __restrict__ W)
{
    extern __shared__ float smem[];          // 2 buffers * 18432 floats
    const int tid  = threadIdx.x;
    const int wid  = tid >> 5;
    const int lane = tid & 31;
    const int wm   = wid & 3;                // 0..3
    const int wn   = wid >> 2;               // 0..1
    const int bm   = blockIdx.x * 128;
    const int bn   = blockIdx.y * 128;

    float acc[2][8][4];
    #pragma unroll
    for (int mt = 0; mt < 2; mt++)
        #pragma unroll
        for (int nt = 0; nt < 8; nt++)
            #pragma unroll
            for (int j = 0; j < 4; j++) acc[mt][nt][j] = 0.f;

    {
        LdgRegs r0;
        ldg_chunk(r0, X, W, bm, bn, 0, tid);
        sts_chunk(smem, r0, tid);
    }
    __syncthreads();

    #pragma unroll 1
    for (int ck = 0; ck < 16; ck++) {
        const int cur = ck & 1;
        LdgRegs nr;
        if (ck < 15) ldg_chunk(nr, X, W, bm, bn, ck + 1, tid);   // LDGs in flight
        compute_chunk(smem + cur * BUleF, acc, wm, wn, lane);     // overlap with LDG
        if (ck < 15) sts_chunk(smem + (cur ^ 1) * BUleF, nr, tid);
        __syncthreads();
    }

    // Epilogue: direct float2 stores to g_I
    #pragma unroll
    for (int mt = 0; mt < 2; mt++) {
        const int r0 = bm + wm * 32 + mt * 16 + (lane >> 2);
        #pragma unroll
        for (int nt = 0; nt < 8; nt++) {
            const int c = bn + wn * 64 + nt * 8 + 2 * (lane & 3);
            *(float2*)(g_I + (size_t)r0 * NDIM + c)       = make_float2(acc[mt][nt][0], acc[mt][nt][1]);
            *(float2*)(g_I + (size_t)(r0 + 8) * NDIM + c) = make_float2(acc[mt][nt][2], acc[mt][nt][3]);
        }
    }
}

// ---------------------------------------------------------------------------
// Kernel 2: per-neuron Izhikevich scan (unchanged — proven correct in R1)
// ---------------------------------------------------------------------------
struct NeuronP { float TS, V2, V1, V0, KA, Bp, TH, Cc, D; };

__device__ __forceinline__ void snn_step(float Ic, int t, int g,
                                         const NeuronP& P, float& u, float& v,
                                         float* __restrict__ out)
{
    float t0 = P.V0 - u + Ic;
    t0 = fmaf(P.V1, v, t0);
    t0 = fmaf(P.V2, v * v, t0);
    const float vn = fmaf(P.TS, t0, v);
    const float un = fmaf(P.KA, fmaf(P.Bp, v, -u), u);
    const bool  sp = (vn - P.TH) > 0.f;
    const float s  = sp ? 1.f : 0.f;
    const float vo = sp ? P.Cc : vn;
    const float uo = sp ? (un + P.D) : un;

    out[(size_t)t * PLANE + g] = s;
    const size_t sb = STATES_OFF + (size_t)t * (3 * PLANE) + g;
    out[sb]             = uo;
    out[sb + PLANE]     = vo;
    out[sb + 2 * PLANE] = s;
    u = uo; v = vo;
}

__global__ __launch_bounds__(128) void scan_kernel(
    const float* __restrict__ st,
    const float* __restrict__ pa,  const float* __restrict__ pb,
    const float* __restrict__ pc,  const float* __restrict__ pd,
    const float* __restrict__ pv2, const float* __restrict__ pv1,
    const float* __restrict__ pv0, const float* __restrict__ ptau,
    const float* __restrict__ pth, const float* __restrict__ pts,
    float* __restrict__ out)
{
    const int g = blockIdx.x * 128 + threadIdx.x;
    const int n = g & (NDIM - 1);

    NeuronP P;
    P.TS = pts[n];
    P.V2 = pv2[n]; P.V1 = pv1[n]; P.V0 = pv0[n];
    P.KA = P.TS / ptau[n] * pa[n];
    P.Bp = pb[n]; P.TH = pth[n]; P.Cc = pc[n]; P.D = pd[n];

    float u = st[g];
    float v = st[PLANE + g];

    const float* Ip = g_I + (size_t)(g >> 9) * ((size_t)T_STEPS * NDIM) + n;

    float bufA[8], bufB[8];
    #pragma unroll
    for (int p = 0; p < 8; p++) bufA[p] = Ip[(size_t)p * NDIM];

    #pragma unroll 1
    for (int t0 = 0; t0 < 992; t0 += 16) {
        #pragma unroll
        for (int p = 0; p < 8; p++) bufB[p] = Ip[(size_t)(t0 + 8 + p) * NDIM];
        #pragma unroll
        for (int p = 0; p < 8; p++) snn_step(bufA[p], t0 + p, g, P, u, v, out);
        #pragma unroll
        for (int p = 0; p < 8; p++) bufA[p] = Ip[(size_t)(t0 + 16 + p) * NDIM];
        #pragma unroll
        for (int p = 0; p < 8; p++) snn_step(bufB[p], t0 + 8 + p, g, P, u, v, out);
    }
    #pragma unroll
    for (int p = 0; p < 8; p++) snn_step(bufA[p], 992 + p, g, P, u, v, out);
}

// ---------------------------------------------------------------------------
// Kernel 3: r[t*B+b] = sum_n s[t,b,n] * W2[n]
// ---------------------------------------------------------------------------
__global__ __launch_bounds__(128) void readout_reduce_kernel(
    const float* __restrict__ out, const float* __restrict__ W2)
{
    const int tb = blockIdx.x;
    const float* sp = out + (size_t)tb * NDIM;
    const int tid = threadIdx.x;

    float sum = 0.f;
    #pragma unroll
    for (int j = 0; j < 4; j++) {
        const int n = tid + j * 128;
        sum = fmaf(sp[n], W2[n], sum);
    }
    #pragma unroll
    for (int o = 16; o > 0; o >>= 1)
        sum += __shfl_xor_sync(0xffffffffu, sum, o);

    __shared__ float ws[4];
    if ((tid & 31) == 0) ws[tid >> 5] = sum;
    __syncthreads();
    if (tid == 0) g_r[tb] = (ws[0] + ws[1]) + (ws[2] + ws[3]);
}

// ---------------------------------------------------------------------------
// Kernel 4: li recurrence — warp-parallel linear-recurrence scan, 1 warp per b.
// ---------------------------------------------------------------------------
__global__ void li_kernel(const float* __restrict__ stLI,
                          const float* __restrict__ leak,
                          float* __restrict__ out)
{
    const int b = blockIdx.x;
    const int lane = threadIdx.x;    // 32 threads
    const float lk = leak[0];
    const float l1 = lk, l2 = l1 * l1, l4 = l2 * l2, l8 = l4 * l4, l16 = l8 * l8;
    float lpow = lk;                 // leak^(lane+1)
    for (int i = 0; i < 5; i++) {
        float sq[5] = {l1, l2, l4, l8, l16};
        if ((lane >> i) & 1) lpow *= sq[i];
    }
    // lpow currently lk * product of bits -> equals lk^(1+lane). (lane bits select powers)

    float carry = stLI[b];
    float x = g_r[lane * BATCH + b];

    #pragma unroll 1
    for (int t0 = 0; t0 < T_STEPS; t0 += 32) {
        const int tn = t0 + 32 + lane;
        const float xn = (tn < T_STEPS) ? g_r[tn * BATCH + b] : 0.f;

        float y = x, up;
        up = __shfl_up_sync(0xffffffffu, y, 1);  if (lane >= 1)  y = fmaf(l1,  up, y);
        up = __shfl_up_sync(0xffffffffu, y, 2);  if (lane >= 2)  y = fmaf(l2,  up, y);
        up = __shfl_up_sync(0xffffffffu, y, 4);  if (lane >= 4)  y = fmaf(l4,  up, y);
        up = __shfl_up_sync(0xffffffffu, y, 8);  if (lane >= 8)  y = fmaf(l8,  up, y);
        up = __shfl_up_sync(0xffffffffu, y, 16); if (lane >= 16) y = fmaf(l16, up, y);

        const float li = fmaf(lpow, carry, y);
        if (t0 + lane < T_STEPS)
            out[DEC_OFF + (size_t)(t0 + lane) * BATCH + b] = li;
        carry = __shfl_sync(0xffffffffu, li, 31);
        x = xn;
    }
}

// ---------------------------------------------------------------------------
extern "C" void kernel_launch(void* const* d_in, const int* in_sizes, int n_in,
                              void* d_out, int out_size)
{
    const float* x    = (const float*)d_in[0];
    const float* st   = (const float*)d_in[1];
    const float* stLI = (const float*)d_in[2];
    const float* W1   = (const float*)d_in[3];
    const float* W2   = (const float*)d_in[4];
    const float* a_   = (const float*)d_in[5];
    const float* b_   = (const float*)d_in[6];
    const float* c_   = (const float*)d_in[7];
    const float* d_   = (const float*)d_in[8];
    const float* v2_  = (const float*)d_in[9];
    const float* v1_  = (const float*)d_in[10];
    const float* v0_  = (const float*)d_in[11];
    const float* tau_ = (const float*)d_in[12];
    const float* th_  = (const float*)d_in[13];
    const float* lk_  = (const float*)d_in[14];
    const float* ts_  = (const float*)d_in[15];
    float* out = (float*)d_out;

    const int smem_bytes = 2 * BUleF * (int)sizeof(float);   // 147456
    cudaFuncSetAttribute(gemm_tf32_kernel,
                         cudaFuncAttributeMaxDynamicSharedMemorySize, smem_bytes);

    dim3 ggrid(MROWS / 128, NDIM / 128);   // (500, 4)
    gemm_tf32_kernel<<<ggrid, 256, smem_bytes>>>(x, W1);
    scan_kernel<<<(BATCH * NDIM) / 128, 128>>>(st, a_, b_, c_, d_, v2_, v1_,
                                               v0_, tau_, th_, ts_, out);
    readout_reduce_kernel<<<T_STEPS * BATCH, 128>>>(out, W2);
    li_kernel<<<BATCH, 32>>>(stLI, lk_, out);
}